// round 1
// baseline (speedup 1.0000x reference)
#include <cuda_runtime.h>
#include <cuda_bf16.h>
#include <math.h>

// Problem constants
#define T_STEPS 512
#define BATCH   128
#define HDIM    512
#define HDIM3   1536

// ---------------------------------------------------------------------------
// Scratch (no allocations allowed): gi buffer [T, B, 3H] = 384 MB,
// h ping-pong buffers stored TRANSPOSED: h[k*128 + b], and barrier state.
// ---------------------------------------------------------------------------
__device__ __align__(16) float g_gi[(size_t)T_STEPS * BATCH * HDIM3];
__device__ __align__(16) float g_h[2][BATCH * HDIM];
__device__ unsigned int g_arrive = 0;
__device__ unsigned int g_release = 0;

// ---------------------------------------------------------------------------
// Grid-wide sense-reversing barrier (all blocks guaranteed co-resident:
// grid = 128 blocks <= SM count, tiny resource footprint).
// ---------------------------------------------------------------------------
__device__ __forceinline__ void grid_barrier(int nblk) {
    __syncthreads();
    if (threadIdx.x == 0) {
        __threadfence();  // make prior global writes visible
        unsigned gen = atomicAdd(&g_release, 0u);  // ordered read of generation
        unsigned ticket = atomicAdd(&g_arrive, 1u);
        if (ticket == (unsigned)(nblk - 1)) {
            atomicExch(&g_arrive, 0u);
            __threadfence();
            atomicAdd(&g_release, 1u);
        } else {
            while (*((volatile unsigned int*)&g_release) == gen) {
                __nanosleep(32);
            }
        }
        __threadfence();
    }
    __syncthreads();
}

// ---------------------------------------------------------------------------
// Pre-GEMM: gi[m, n] = sum_k x[m,k] * Wi[k,n] + bi[n]
// M = T*B = 65536, N = 1536, K = 512.
// Classic 128x128 tile, 16-deep K chunks, 8x8 per thread, 256 threads.
// ---------------------------------------------------------------------------
#define BM 128
#define BN 128
#define BKK 16

__global__ __launch_bounds__(256) void gemm_gi_kernel(
    const float* __restrict__ X, const float* __restrict__ Wi,
    const float* __restrict__ bi, float* __restrict__ gi)
{
    __shared__ __align__(16) float As[BKK][BM];  // transposed A tile
    __shared__ __align__(16) float Bs[BKK][BN];

    const int m0 = blockIdx.y * BM;
    const int n0 = blockIdx.x * BN;
    const int tid = threadIdx.x;

    // A tile load mapping: [BM][BKK] -> float4 per thread, 2 row-halves
    const int arow = tid >> 2;          // 0..63
    const int acol = (tid & 3) * 4;     // 0,4,8,12
    // B tile load mapping: [BKK][BN]
    const int brow = tid >> 5;          // 0..7
    const int bcol = (tid & 31) * 4;

    const int tr = tid >> 4;            // 0..15
    const int tc = tid & 15;            // 0..15

    float acc[8][8];
#pragma unroll
    for (int i = 0; i < 8; i++)
#pragma unroll
        for (int j = 0; j < 8; j++) acc[i][j] = 0.f;

    for (int k0 = 0; k0 < HDIM; k0 += BKK) {
#pragma unroll
        for (int h = 0; h < 2; h++) {
            int r = arow + 64 * h;
            float4 v = *(const float4*)&X[(size_t)(m0 + r) * HDIM + k0 + acol];
            As[acol + 0][r] = v.x;
            As[acol + 1][r] = v.y;
            As[acol + 2][r] = v.z;
            As[acol + 3][r] = v.w;
        }
#pragma unroll
        for (int h = 0; h < 2; h++) {
            int r = brow + 8 * h;
            *(float4*)&Bs[r][bcol] =
                *(const float4*)&Wi[(size_t)(k0 + r) * HDIM3 + n0 + bcol];
        }
        __syncthreads();

#pragma unroll
        for (int k = 0; k < BKK; k++) {
            float4 a0 = *(const float4*)&As[k][tr * 8];
            float4 a1 = *(const float4*)&As[k][tr * 8 + 4];
            float4 b0 = *(const float4*)&Bs[k][tc * 8];
            float4 b1 = *(const float4*)&Bs[k][tc * 8 + 4];
            float af[8] = {a0.x, a0.y, a0.z, a0.w, a1.x, a1.y, a1.z, a1.w};
            float bf[8] = {b0.x, b0.y, b0.z, b0.w, b1.x, b1.y, b1.z, b1.w};
#pragma unroll
            for (int i = 0; i < 8; i++)
#pragma unroll
                for (int j = 0; j < 8; j++) acc[i][j] += af[i] * bf[j];
        }
        __syncthreads();
    }

    // Epilogue with bias
#pragma unroll
    for (int i = 0; i < 8; i++) {
        int m = m0 + tr * 8 + i;
#pragma unroll
        for (int j = 0; j < 8; j += 4) {
            int n = n0 + tc * 8 + j;
            float4 o;
            o.x = acc[i][j + 0] + bi[n + 0];
            o.y = acc[i][j + 1] + bi[n + 1];
            o.z = acc[i][j + 2] + bi[n + 2];
            o.w = acc[i][j + 3] + bi[n + 3];
            *(float4*)&gi[(size_t)m * HDIM3 + n] = o;
        }
    }
}

// ---------------------------------------------------------------------------
// Persistent scan kernel: 128 blocks x 128 threads.
// Block bid owns h-columns j0..j0+3 (so Wh columns {j0.., 512+j0.., 1024+j0..}).
// Thread tid = batch row b. One grid barrier per timestep (ping-pong h).
// ---------------------------------------------------------------------------
#define SCAN_BLOCKS 128
#define JCHUNK 4

__device__ __forceinline__ float sigmoidf_(float x) {
    return 1.0f / (1.0f + expf(-x));
}

__global__ __launch_bounds__(128) void scan_kernel(
    const float* __restrict__ h0, const float* __restrict__ Wh,
    const float* __restrict__ bhn,
    float* __restrict__ out_h, float* __restrict__ out_ys)
{
    __shared__ __align__(16) float wh_s[HDIM * 12];  // 24 KB, loop-invariant

    const int tid = threadIdx.x;          // batch row b
    const int j0 = blockIdx.x * JCHUNK;

    // Load this block's 12 Wh columns into smem (once).
    for (int idx = tid; idx < HDIM * 12; idx += 128) {
        int kk = idx / 12;
        int c = idx - kk * 12;
        int col = (c >> 2) * HDIM + j0 + (c & 3);
        wh_s[idx] = Wh[(size_t)kk * HDIM3 + col];
    }

    float bn[JCHUNK];
#pragma unroll
    for (int c = 0; c < JCHUNK; c++) bn[c] = bhn[j0 + c];

    // Init h: transpose h0 chunk into g_h[0][k*128 + b]; keep own chunk in regs.
    float hn[JCHUNK];
    {
        float4 v = *(const float4*)&h0[(size_t)tid * HDIM + j0];
        hn[0] = v.x; hn[1] = v.y; hn[2] = v.z; hn[3] = v.w;
#pragma unroll
        for (int c = 0; c < JCHUNK; c++)
            g_h[0][(j0 + c) * BATCH + tid] = hn[c];
    }
    grid_barrier(SCAN_BLOCKS);

    for (int t = 0; t < T_STEPS; t++) {
        const float* __restrict__ hp = g_h[t & 1];
        float* __restrict__ hq = g_h[(t & 1) ^ 1];

        float acc[12];
#pragma unroll
        for (int c = 0; c < 12; c++) acc[c] = 0.f;

        // gh(tile) = h @ Wh(cols): software-pipelined coalesced L2 loads of h.
        float hv[8];
#pragma unroll
        for (int u = 0; u < 8; u++) hv[u] = hp[u * BATCH + tid];

#pragma unroll 1
        for (int base = 0; base < HDIM; base += 8) {
            float hv_n[8];
            if (base + 8 < HDIM) {
#pragma unroll
                for (int u = 0; u < 8; u++)
                    hv_n[u] = hp[(base + 8 + u) * BATCH + tid];
            }
#pragma unroll
            for (int u = 0; u < 8; u++) {
                const float4* w = (const float4*)(wh_s + (base + u) * 12);
                float4 w0 = w[0], w1 = w[1], w2 = w[2];
                float h_ = hv[u];
                acc[0] += h_ * w0.x; acc[1] += h_ * w0.y;
                acc[2] += h_ * w0.z; acc[3] += h_ * w0.w;
                acc[4] += h_ * w1.x; acc[5] += h_ * w1.y;
                acc[6] += h_ * w1.z; acc[7] += h_ * w1.w;
                acc[8] += h_ * w2.x; acc[9] += h_ * w2.y;
                acc[10] += h_ * w2.z; acc[11] += h_ * w2.w;
            }
#pragma unroll
            for (int u = 0; u < 8; u++) hv[u] = hv_n[u];
        }

        // Gate update for our 4 columns. gi layout: [t, b, 3H].
        const float* gi = &g_gi[((size_t)t * BATCH + tid) * HDIM3];
        float4 gr = *(const float4*)&gi[j0];
        float4 gz = *(const float4*)&gi[HDIM + j0];
        float4 gn = *(const float4*)&gi[2 * HDIM + j0];
        float giR[4] = {gr.x, gr.y, gr.z, gr.w};
        float giZ[4] = {gz.x, gz.y, gz.z, gz.w};
        float giN[4] = {gn.x, gn.y, gn.z, gn.w};

#pragma unroll
        for (int c = 0; c < JCHUNK; c++) {
            float r = sigmoidf_(giR[c] + acc[c]);
            float z = sigmoidf_(giZ[c] + acc[4 + c]);
            float n = tanhf(giN[c] + r * (acc[8 + c] + bn[c]));
            float hnew = (1.0f - z) * n + z * hn[c];  // hn[c] = h_{t-1} own chunk
            hn[c] = hnew;
            hq[(j0 + c) * BATCH + tid] = hnew;
        }

        // ys[t, b, j0..j0+3]
        float4 yo = make_float4(hn[0], hn[1], hn[2], hn[3]);
        *(float4*)&out_ys[((size_t)t * BATCH + tid) * HDIM + j0] = yo;

        grid_barrier(SCAN_BLOCKS);
    }

    if (out_h) {
        *(float4*)&out_h[(size_t)tid * HDIM + j0] =
            make_float4(hn[0], hn[1], hn[2], hn[3]);
    }
}

// ---------------------------------------------------------------------------
// kernel_launch: inputs per metadata order: x, h0, Wi, bi, Wh, bhn
// ---------------------------------------------------------------------------
extern "C" void kernel_launch(void* const* d_in, const int* in_sizes, int n_in,
                              void* d_out, int out_size)
{
    const float* x   = (const float*)d_in[0];   // [T, B, H]
    const float* h0  = (const float*)d_in[1];   // [B, H]
    const float* Wi  = (const float*)d_in[2];   // [H, 3H]
    const float* bi  = (const float*)d_in[3];   // [3H]
    const float* Wh  = (const float*)d_in[4];   // [H, 3H]
    const float* bhn = (const float*)d_in[5];   // [H]

    float* out = (float*)d_out;
    float* out_h;
    float* out_ys;
    const long long ys_elems = (long long)T_STEPS * BATCH * HDIM;
    if ((long long)out_size >= ys_elems + (long long)BATCH * HDIM) {
        out_h = out;                    // (h_final, ys) flattened in order
        out_ys = out + (size_t)BATCH * HDIM;
    } else {
        out_h = nullptr;                // ys only
        out_ys = out;
    }

    float* gi;
    cudaGetSymbolAddress((void**)&gi, g_gi);

    // 1) gi = x @ Wi + bi
    dim3 ggrid(HDIM3 / BN, (T_STEPS * BATCH) / BM);
    gemm_gi_kernel<<<ggrid, 256>>>(x, Wi, bi, gi);

    // 2) persistent GRU scan
    scan_kernel<<<SCAN_BLOCKS, 128>>>(h0, Wh, bhn, out_h, out_ys);
}

// round 2
// speedup vs baseline: 1.5197x; 1.5197x over previous
#include <cuda_runtime.h>
#include <cuda_bf16.h>
#include <math.h>

// Problem constants
#define T_STEPS 512
#define BATCH   128
#define HDIM    512
#define HDIM3   1536

// ---------------------------------------------------------------------------
// Scratch (no allocations allowed): gi buffer [T, B, 3H] = 384 MB,
// h ping-pong buffers stored TRANSPOSED: h[k*128 + b], and barrier state.
// ---------------------------------------------------------------------------
__device__ __align__(16) float g_gi[(size_t)T_STEPS * BATCH * HDIM3];
__device__ __align__(16) float g_h[2][BATCH * HDIM];
__device__ unsigned int g_arrive = 0;
__device__ unsigned int g_release = 0;

// ---------------------------------------------------------------------------
// Grid-wide sense-reversing barrier (all blocks co-resident: 128 <= #SMs).
// ---------------------------------------------------------------------------
__device__ __forceinline__ void grid_barrier(int nblk) {
    __syncthreads();
    if (threadIdx.x == 0) {
        __threadfence();  // make prior global writes visible
        unsigned gen = atomicAdd(&g_release, 0u);  // ordered read of generation
        unsigned ticket = atomicAdd(&g_arrive, 1u);
        if (ticket == (unsigned)(nblk - 1)) {
            atomicExch(&g_arrive, 0u);
            __threadfence();
            atomicAdd(&g_release, 1u);
        } else {
            while (*((volatile unsigned int*)&g_release) == gen) {
                __nanosleep(32);
            }
        }
        __threadfence();
    }
    __syncthreads();
}

// ---------------------------------------------------------------------------
// Pre-GEMM: gi[m, n] = sum_k x[m,k] * Wi[k,n] + bi[n]
// M = T*B = 65536, N = 1536, K = 512. 128x128 tile, 8x8/thread, 256 threads.
// ---------------------------------------------------------------------------
#define BM 128
#define BN 128
#define BKK 16

__global__ __launch_bounds__(256) void gemm_gi_kernel(
    const float* __restrict__ X, const float* __restrict__ Wi,
    const float* __restrict__ bi, float* __restrict__ gi)
{
    __shared__ __align__(16) float As[BKK][BM];  // transposed A tile
    __shared__ __align__(16) float Bs[BKK][BN];

    const int m0 = blockIdx.y * BM;
    const int n0 = blockIdx.x * BN;
    const int tid = threadIdx.x;

    const int arow = tid >> 2;          // 0..63
    const int acol = (tid & 3) * 4;     // 0,4,8,12
    const int brow = tid >> 5;          // 0..7
    const int bcol = (tid & 31) * 4;

    const int tr = tid >> 4;            // 0..15
    const int tc = tid & 15;            // 0..15

    float acc[8][8];
#pragma unroll
    for (int i = 0; i < 8; i++)
#pragma unroll
        for (int j = 0; j < 8; j++) acc[i][j] = 0.f;

    for (int k0 = 0; k0 < HDIM; k0 += BKK) {
#pragma unroll
        for (int h = 0; h < 2; h++) {
            int r = arow + 64 * h;
            float4 v = *(const float4*)&X[(size_t)(m0 + r) * HDIM + k0 + acol];
            As[acol + 0][r] = v.x;
            As[acol + 1][r] = v.y;
            As[acol + 2][r] = v.z;
            As[acol + 3][r] = v.w;
        }
#pragma unroll
        for (int h = 0; h < 2; h++) {
            int r = brow + 8 * h;
            *(float4*)&Bs[r][bcol] =
                *(const float4*)&Wi[(size_t)(k0 + r) * HDIM3 + n0 + bcol];
        }
        __syncthreads();

#pragma unroll
        for (int k = 0; k < BKK; k++) {
            float4 a0 = *(const float4*)&As[k][tr * 8];
            float4 a1 = *(const float4*)&As[k][tr * 8 + 4];
            float4 b0 = *(const float4*)&Bs[k][tc * 8];
            float4 b1 = *(const float4*)&Bs[k][tc * 8 + 4];
            float af[8] = {a0.x, a0.y, a0.z, a0.w, a1.x, a1.y, a1.z, a1.w};
            float bf[8] = {b0.x, b0.y, b0.z, b0.w, b1.x, b1.y, b1.z, b1.w};
#pragma unroll
            for (int i = 0; i < 8; i++)
#pragma unroll
                for (int j = 0; j < 8; j++) acc[i][j] += af[i] * bf[j];
        }
        __syncthreads();
    }

#pragma unroll
    for (int i = 0; i < 8; i++) {
        int m = m0 + tr * 8 + i;
#pragma unroll
        for (int j = 0; j < 8; j += 4) {
            int n = n0 + tc * 8 + j;
            float4 o;
            o.x = acc[i][j + 0] + bi[n + 0];
            o.y = acc[i][j + 1] + bi[n + 1];
            o.z = acc[i][j + 2] + bi[n + 2];
            o.w = acc[i][j + 3] + bi[n + 3];
            *(float4*)&gi[(size_t)m * HDIM3 + n] = o;
        }
    }
}

// ---------------------------------------------------------------------------
// Persistent scan kernel: 128 blocks x 256 threads (2 warps/SMSP -> FFMA
// pipe can saturate). Block bid owns h-columns j0..j0+3. Threads are split
// into two halves over the k-reduction: half = tid>>7 handles k in
// [half*256, half*256+256). Half-1 dumps partial accumulators to smem;
// half-0 reduces, applies gates, writes h and ys. One grid barrier per step.
// ---------------------------------------------------------------------------
#define SCAN_BLOCKS 128
#define SCAN_THREADS 256
#define KSPLIT 256           // k per half
#define JCHUNK 4

__device__ __forceinline__ float fast_sigmoid(float x) {
    return 1.0f / (1.0f + __expf(-x));
}
__device__ __forceinline__ float fast_tanh(float x) {
    // tanh(x) = 2*sigmoid(2x) - 1
    return 2.0f / (1.0f + __expf(-2.0f * x)) - 1.0f;
}

__global__ __launch_bounds__(SCAN_THREADS) void scan_kernel(
    const float* __restrict__ h0, const float* __restrict__ Wh,
    const float* __restrict__ bhn,
    float* __restrict__ out_h, float* __restrict__ out_ys)
{
    __shared__ __align__(16) float wh_s[HDIM * 12];   // 24 KB, loop-invariant
    __shared__ __align__(16) float red_s[12 * BATCH]; // 6 KB partial-acc dump

    const int tid = threadIdx.x;
    const int b = tid & (BATCH - 1);      // batch row
    const int half = tid >> 7;            // 0 or 1
    const int kbase = half * KSPLIT;
    const int j0 = blockIdx.x * JCHUNK;

    // Load this block's 12 Wh columns into smem (once). Layout: wh_s[k*12+c],
    // c = gate*4 + cc, columns j0..j0+3 of gates r,z,n.
    for (int idx = tid; idx < HDIM * 12; idx += SCAN_THREADS) {
        int kk = idx / 12;
        int c = idx - kk * 12;
        int col = (c >> 2) * HDIM + j0 + (c & 3);
        wh_s[idx] = Wh[(size_t)kk * HDIM3 + col];
    }

    float bn[JCHUNK];
#pragma unroll
    for (int c = 0; c < JCHUNK; c++) bn[c] = bhn[j0 + c];

    // Init h: half-0 transposes h0 chunk into g_h[0] and keeps it in regs.
    float hn[JCHUNK];
    {
        float4 v = *(const float4*)&h0[(size_t)b * HDIM + j0];
        hn[0] = v.x; hn[1] = v.y; hn[2] = v.z; hn[3] = v.w;
        if (half == 0) {
#pragma unroll
            for (int c = 0; c < JCHUNK; c++)
                g_h[0][(j0 + c) * BATCH + b] = hn[c];
        }
    }
    grid_barrier(SCAN_BLOCKS);

    for (int t = 0; t < T_STEPS; t++) {
        const float* __restrict__ hp = g_h[t & 1];
        float* __restrict__ hq = g_h[(t & 1) ^ 1];

        // Early-issue gi loads (independent of h -> overlap with GEMM).
        const float* gi = &g_gi[((size_t)t * BATCH + b) * HDIM3];
        float4 gr = *(const float4*)&gi[j0];
        float4 gz = *(const float4*)&gi[HDIM + j0];
        float4 gn = *(const float4*)&gi[2 * HDIM + j0];

        float acc[12];
#pragma unroll
        for (int c = 0; c < 12; c++) acc[c] = 0.f;

        // gh(tile) partial = h[kbase:kbase+256] @ Wh rows, pipelined L2 loads.
        float hv[8];
#pragma unroll
        for (int u = 0; u < 8; u++) hv[u] = hp[(kbase + u) * BATCH + b];

#pragma unroll 1
        for (int base = 0; base < KSPLIT; base += 8) {
            float hv_n[8];
            if (base + 8 < KSPLIT) {
#pragma unroll
                for (int u = 0; u < 8; u++)
                    hv_n[u] = hp[(kbase + base + 8 + u) * BATCH + b];
            }
#pragma unroll
            for (int u = 0; u < 8; u++) {
                const float4* w = (const float4*)(wh_s + (kbase + base + u) * 12);
                float4 w0 = w[0], w1 = w[1], w2 = w[2];
                float h_ = hv[u];
                acc[0] += h_ * w0.x; acc[1] += h_ * w0.y;
                acc[2] += h_ * w0.z; acc[3] += h_ * w0.w;
                acc[4] += h_ * w1.x; acc[5] += h_ * w1.y;
                acc[6] += h_ * w1.z; acc[7] += h_ * w1.w;
                acc[8] += h_ * w2.x; acc[9] += h_ * w2.y;
                acc[10] += h_ * w2.z; acc[11] += h_ * w2.w;
            }
#pragma unroll
            for (int u = 0; u < 8; u++) hv[u] = hv_n[u];
        }

        // Cross-half reduction: half-1 dumps, half-0 combines.
        if (half == 1) {
#pragma unroll
            for (int c = 0; c < 12; c++) red_s[c * BATCH + b] = acc[c];
        }
        __syncthreads();

        if (half == 0) {
#pragma unroll
            for (int c = 0; c < 12; c++) acc[c] += red_s[c * BATCH + b];

            float giR[4] = {gr.x, gr.y, gr.z, gr.w};
            float giZ[4] = {gz.x, gz.y, gz.z, gz.w};
            float giN[4] = {gn.x, gn.y, gn.z, gn.w};

#pragma unroll
            for (int c = 0; c < JCHUNK; c++) {
                float r = fast_sigmoid(giR[c] + acc[c]);
                float z = fast_sigmoid(giZ[c] + acc[4 + c]);
                float n = fast_tanh(giN[c] + r * (acc[8 + c] + bn[c]));
                float hnew = (1.0f - z) * n + z * hn[c];
                hn[c] = hnew;
                hq[(j0 + c) * BATCH + b] = hnew;
            }

            // ys[t, b, j0..j0+3]
            *(float4*)&out_ys[((size_t)t * BATCH + b) * HDIM + j0] =
                make_float4(hn[0], hn[1], hn[2], hn[3]);
        }

        grid_barrier(SCAN_BLOCKS);
    }

    if (out_h && half == 0) {
        *(float4*)&out_h[(size_t)b * HDIM + j0] =
            make_float4(hn[0], hn[1], hn[2], hn[3]);
    }
}

// ---------------------------------------------------------------------------
// kernel_launch: inputs per metadata order: x, h0, Wi, bi, Wh, bhn
// ---------------------------------------------------------------------------
extern "C" void kernel_launch(void* const* d_in, const int* in_sizes, int n_in,
                              void* d_out, int out_size)
{
    const float* x   = (const float*)d_in[0];   // [T, B, H]
    const float* h0  = (const float*)d_in[1];   // [B, H]
    const float* Wi  = (const float*)d_in[2];   // [H, 3H]
    const float* bi  = (const float*)d_in[3];   // [3H]
    const float* Wh  = (const float*)d_in[4];   // [H, 3H]
    const float* bhn = (const float*)d_in[5];   // [H]

    float* out = (float*)d_out;
    float* out_h;
    float* out_ys;
    const long long ys_elems = (long long)T_STEPS * BATCH * HDIM;
    if ((long long)out_size >= ys_elems + (long long)BATCH * HDIM) {
        out_h = out;                    // (h_final, ys) flattened in order
        out_ys = out + (size_t)BATCH * HDIM;
    } else {
        out_h = nullptr;                // ys only
        out_ys = out;
    }

    float* gi;
    cudaGetSymbolAddress((void**)&gi, g_gi);

    // 1) gi = x @ Wi + bi
    dim3 ggrid(HDIM3 / BN, (T_STEPS * BATCH) / BM);
    gemm_gi_kernel<<<ggrid, 256>>>(x, Wi, bi, gi);

    // 2) persistent GRU scan
    scan_kernel<<<SCAN_BLOCKS, SCAN_THREADS>>>(h0, Wh, bhn, out_h, out_ys);
}

// round 4
// speedup vs baseline: 1.6187x; 1.0652x over previous
#include <cuda_runtime.h>
#include <cuda_bf16.h>
#include <math.h>

// Problem constants
#define T_STEPS 512
#define BATCH   128
#define HDIM    512
#define HDIM3   1536

// ---------------------------------------------------------------------------
// Packed f32x2 helpers (Blackwell fma.rn.f32x2 — 2 FMAs per instruction).
// ---------------------------------------------------------------------------
__device__ __forceinline__ unsigned long long pk2_(float lo, float hi) {
    unsigned long long r;
    asm("mov.b64 %0, {%1, %2};"
        : "=l"(r) : "r"(__float_as_uint(lo)), "r"(__float_as_uint(hi)));
    return r;
}
__device__ __forceinline__ void upk2_(unsigned long long v, float& lo, float& hi) {
    unsigned int a, b_;
    asm("mov.b64 {%0, %1}, %2;" : "=r"(a), "=r"(b_) : "l"(v));
    lo = __uint_as_float(a);
    hi = __uint_as_float(b_);
}
__device__ __forceinline__ unsigned long long ffma2_(
    unsigned long long a, unsigned long long b, unsigned long long c) {
    unsigned long long d;
    asm("fma.rn.f32x2 %0, %1, %2, %3;" : "=l"(d) : "l"(a), "l"(b), "l"(c));
    return d;
}
__device__ __forceinline__ unsigned long long fadd2_(
    unsigned long long a, unsigned long long b) {
    unsigned long long d;
    asm("add.rn.f32x2 %0, %1, %2;" : "=l"(d) : "l"(a), "l"(b));
    return d;
}

// ---------------------------------------------------------------------------
// Scratch: gi buffer [T, B, 3H], h ping-pong (TRANSPOSED: h[k*128+b]), barrier.
// ---------------------------------------------------------------------------
__device__ __align__(16) float g_gi[(size_t)T_STEPS * BATCH * HDIM3];
__device__ __align__(16) float g_h[2][BATCH * HDIM];
__device__ unsigned int g_arrive = 0;
__device__ unsigned int g_release = 0;

// ---------------------------------------------------------------------------
// Grid-wide sense-reversing barrier (all blocks co-resident: 128 <= #SMs).
// ---------------------------------------------------------------------------
__device__ __forceinline__ void grid_barrier(int nblk) {
    __syncthreads();
    if (threadIdx.x == 0) {
        __threadfence();
        unsigned gen = atomicAdd(&g_release, 0u);
        unsigned ticket = atomicAdd(&g_arrive, 1u);
        if (ticket == (unsigned)(nblk - 1)) {
            atomicExch(&g_arrive, 0u);
            __threadfence();
            atomicAdd(&g_release, 1u);
        } else {
            while (*((volatile unsigned int*)&g_release) == gen) {
                __nanosleep(16);
            }
        }
        __threadfence();
    }
    __syncthreads();
}

// ---------------------------------------------------------------------------
// Pre-GEMM: gi[m,n] = sum_k x[m,k]*Wi[k,n] + bi[n].  M=65536, N=1536, K=512.
// 128x128 tile, 8x8/thread via FFMA2 (8x4 packed accumulators), 256 threads.
// ---------------------------------------------------------------------------
#define BM 128
#define BN 128
#define BKK 16

__global__ __launch_bounds__(256) void gemm_gi_kernel(
    const float* __restrict__ X, const float* __restrict__ Wi,
    const float* __restrict__ bi, float* __restrict__ gi)
{
    __shared__ __align__(16) float As[BKK][BM];  // transposed A tile
    __shared__ __align__(16) float Bs[BKK][BN];

    const int m0 = blockIdx.y * BM;
    const int n0 = blockIdx.x * BN;
    const int tid = threadIdx.x;

    const int arow = tid >> 2;          // 0..63
    const int acol = (tid & 3) * 4;     // 0,4,8,12
    const int brow = tid >> 5;          // 0..7
    const int bcol = (tid & 31) * 4;

    const int tr = tid >> 4;            // 0..15
    const int tc = tid & 15;            // 0..15

    unsigned long long acc2[8][4];
#pragma unroll
    for (int i = 0; i < 8; i++)
#pragma unroll
        for (int j = 0; j < 4; j++) acc2[i][j] = 0ull;

    for (int k0 = 0; k0 < HDIM; k0 += BKK) {
#pragma unroll
        for (int h = 0; h < 2; h++) {
            int r = arow + 64 * h;
            float4 v = *(const float4*)&X[(size_t)(m0 + r) * HDIM + k0 + acol];
            As[acol + 0][r] = v.x;
            As[acol + 1][r] = v.y;
            As[acol + 2][r] = v.z;
            As[acol + 3][r] = v.w;
        }
#pragma unroll
        for (int h = 0; h < 2; h++) {
            int r = brow + 8 * h;
            *(float4*)&Bs[r][bcol] =
                *(const float4*)&Wi[(size_t)(k0 + r) * HDIM3 + n0 + bcol];
        }
        __syncthreads();

#pragma unroll
        for (int k = 0; k < BKK; k++) {
            float4 a0 = *(const float4*)&As[k][tr * 8];
            float4 a1 = *(const float4*)&As[k][tr * 8 + 4];
            float4 b0 = *(const float4*)&Bs[k][tc * 8];
            float4 b1 = *(const float4*)&Bs[k][tc * 8 + 4];
            unsigned long long bv[4] = {
                pk2_(b0.x, b0.y), pk2_(b0.z, b0.w),
                pk2_(b1.x, b1.y), pk2_(b1.z, b1.w)};
            float af[8] = {a0.x, a0.y, a0.z, a0.w, a1.x, a1.y, a1.z, a1.w};
#pragma unroll
            for (int i = 0; i < 8; i++) {
                unsigned long long av = pk2_(af[i], af[i]);
#pragma unroll
                for (int j = 0; j < 4; j++)
                    acc2[i][j] = ffma2_(av, bv[j], acc2[i][j]);
            }
        }
        __syncthreads();
    }

#pragma unroll
    for (int i = 0; i < 8; i++) {
        int m = m0 + tr * 8 + i;
#pragma unroll
        for (int jq = 0; jq < 2; jq++) {
            int n = n0 + tc * 8 + jq * 4;
            float4 o;
            upk2_(acc2[i][jq * 2 + 0], o.x, o.y);
            upk2_(acc2[i][jq * 2 + 1], o.z, o.w);
            o.x += bi[n + 0];
            o.y += bi[n + 1];
            o.z += bi[n + 2];
            o.w += bi[n + 3];
            *(float4*)&gi[(size_t)m * HDIM3 + n] = o;
        }
    }
}

// ---------------------------------------------------------------------------
// Persistent scan: 128 blocks x 512 threads (4 warps/SMSP). Block owns
// h-columns j0..j0+3 (12 Wh columns incl. gates). 4-way k-split: quarter q
// reduces k in [q*128, q*128+128) with packed FFMA2 (6 f32x2 accumulators).
// Quarters 1-3 dump partials to smem; quarter 0 reduces + gates + writes.
// One grid barrier per timestep (ping-pong h).
// ---------------------------------------------------------------------------
#define SCAN_BLOCKS 128
#define SCAN_THREADS 512
#define KSPLIT 128           // k per quarter
#define JCHUNK 4

__device__ __forceinline__ float fast_sigmoid(float x) {
    return 1.0f / (1.0f + __expf(-x));
}
__device__ __forceinline__ float fast_tanh(float x) {
    return 2.0f / (1.0f + __expf(-2.0f * x)) - 1.0f;
}

__global__ __launch_bounds__(SCAN_THREADS) void scan_kernel(
    const float* __restrict__ h0, const float* __restrict__ Wh,
    const float* __restrict__ bhn,
    float* __restrict__ out_h, float* __restrict__ out_ys)
{
    __shared__ __align__(16) float wh_s[HDIM * 12];                // 24 KB
    __shared__ __align__(16) unsigned long long red2[3][6 * BATCH]; // 18 KB

    const int tid = threadIdx.x;
    const int b = tid & (BATCH - 1);      // batch row
    const int quarter = tid >> 7;         // 0..3
    const int kbase = quarter * KSPLIT;
    const int j0 = blockIdx.x * JCHUNK;

    // Load this block's 12 Wh columns into smem once. wh_s[k*12 + c],
    // c = gate*4 + cc (gates r,z,n; columns j0..j0+3).
    for (int idx = tid; idx < HDIM * 12; idx += SCAN_THREADS) {
        int kk = idx / 12;
        int c = idx - kk * 12;
        int col = (c >> 2) * HDIM + j0 + (c & 3);
        wh_s[idx] = Wh[(size_t)kk * HDIM3 + col];
    }

    float bn[JCHUNK];
#pragma unroll
    for (int c = 0; c < JCHUNK; c++) bn[c] = bhn[j0 + c];

    // Init h: quarter 0 transposes h0 chunk into g_h[0] and keeps it in regs.
    float hn[JCHUNK];
    {
        float4 v = *(const float4*)&h0[(size_t)b * HDIM + j0];
        hn[0] = v.x; hn[1] = v.y; hn[2] = v.z; hn[3] = v.w;
        if (quarter == 0) {
#pragma unroll
            for (int c = 0; c < JCHUNK; c++)
                g_h[0][(j0 + c) * BATCH + b] = hn[c];
        }
    }
    grid_barrier(SCAN_BLOCKS);

    for (int t = 0; t < T_STEPS; t++) {
        const float* __restrict__ hp = g_h[t & 1];
        float* __restrict__ hq = g_h[(t & 1) ^ 1];

        // Early-issue gi loads (quarter 0 only — it alone does the gates).
        float4 gr, gz, gn;
        if (quarter == 0) {
            const float* gi = &g_gi[((size_t)t * BATCH + b) * HDIM3];
            gr = *(const float4*)&gi[j0];
            gz = *(const float4*)&gi[HDIM + j0];
            gn = *(const float4*)&gi[2 * HDIM + j0];
        }

        unsigned long long acc2[6];
#pragma unroll
        for (int c = 0; c < 6; c++) acc2[c] = 0ull;

        // Partial gh = h[kbase:kbase+128] @ Wh rows, pipelined L2 loads of h.
        float hv[8];
#pragma unroll
        for (int u = 0; u < 8; u++) hv[u] = hp[(kbase + u) * BATCH + b];

#pragma unroll 1
        for (int base = 0; base < KSPLIT; base += 8) {
            float hv_n[8];
            if (base + 8 < KSPLIT) {
#pragma unroll
                for (int u = 0; u < 8; u++)
                    hv_n[u] = hp[(kbase + base + 8 + u) * BATCH + b];
            }
#pragma unroll
            for (int u = 0; u < 8; u++) {
                const float4* w = (const float4*)(wh_s + (kbase + base + u) * 12);
                float4 w0 = w[0], w1 = w[1], w2 = w[2];
                unsigned long long hv2 = pk2_(hv[u], hv[u]);
                acc2[0] = ffma2_(hv2, pk2_(w0.x, w0.y), acc2[0]);
                acc2[1] = ffma2_(hv2, pk2_(w0.z, w0.w), acc2[1]);
                acc2[2] = ffma2_(hv2, pk2_(w1.x, w1.y), acc2[2]);
                acc2[3] = ffma2_(hv2, pk2_(w1.z, w1.w), acc2[3]);
                acc2[4] = ffma2_(hv2, pk2_(w2.x, w2.y), acc2[4]);
                acc2[5] = ffma2_(hv2, pk2_(w2.z, w2.w), acc2[5]);
            }
#pragma unroll
            for (int u = 0; u < 8; u++) hv[u] = hv_n[u];
        }

        // Cross-quarter reduction: quarters 1-3 dump, quarter 0 combines.
        if (quarter > 0) {
#pragma unroll
            for (int c = 0; c < 6; c++) red2[quarter - 1][c * BATCH + b] = acc2[c];
        }
        __syncthreads();

        if (quarter == 0) {
#pragma unroll
            for (int c = 0; c < 6; c++) {
                acc2[c] = fadd2_(acc2[c], red2[0][c * BATCH + b]);
                acc2[c] = fadd2_(acc2[c], fadd2_(red2[1][c * BATCH + b],
                                                 red2[2][c * BATCH + b]));
            }
            float a[12];
#pragma unroll
            for (int c = 0; c < 6; c++) upk2_(acc2[c], a[2 * c], a[2 * c + 1]);

            float giR[4] = {gr.x, gr.y, gr.z, gr.w};
            float giZ[4] = {gz.x, gz.y, gz.z, gz.w};
            float giN[4] = {gn.x, gn.y, gn.z, gn.w};

#pragma unroll
            for (int c = 0; c < JCHUNK; c++) {
                float r = fast_sigmoid(giR[c] + a[c]);
                float z = fast_sigmoid(giZ[c] + a[4 + c]);
                float n = fast_tanh(giN[c] + r * (a[8 + c] + bn[c]));
                float hnew = (1.0f - z) * n + z * hn[c];
                hn[c] = hnew;
                hq[(j0 + c) * BATCH + b] = hnew;
            }

            *(float4*)&out_ys[((size_t)t * BATCH + b) * HDIM + j0] =
                make_float4(hn[0], hn[1], hn[2], hn[3]);
        }

        grid_barrier(SCAN_BLOCKS);
    }

    if (out_h && quarter == 0) {
        *(float4*)&out_h[(size_t)b * HDIM + j0] =
            make_float4(hn[0], hn[1], hn[2], hn[3]);
    }
}

// ---------------------------------------------------------------------------
// kernel_launch: inputs per metadata order: x, h0, Wi, bi, Wh, bhn
// ---------------------------------------------------------------------------
extern "C" void kernel_launch(void* const* d_in, const int* in_sizes, int n_in,
                              void* d_out, int out_size)
{
    const float* x   = (const float*)d_in[0];   // [T, B, H]
    const float* h0  = (const float*)d_in[1];   // [B, H]
    const float* Wi  = (const float*)d_in[2];   // [H, 3H]
    const float* bi  = (const float*)d_in[3];   // [3H]
    const float* Wh  = (const float*)d_in[4];   // [H, 3H]
    const float* bhn = (const float*)d_in[5];   // [H]

    float* out = (float*)d_out;
    float* out_h;
    float* out_ys;
    const long long ys_elems = (long long)T_STEPS * BATCH * HDIM;
    if ((long long)out_size >= ys_elems + (long long)BATCH * HDIM) {
        out_h = out;                    // (h_final, ys) flattened in order
        out_ys = out + (size_t)BATCH * HDIM;
    } else {
        out_h = nullptr;                // ys only
        out_ys = out;
    }

    float* gi;
    cudaGetSymbolAddress((void**)&gi, g_gi);

    // 1) gi = x @ Wi + bi
    dim3 ggrid(HDIM3 / BN, (T_STEPS * BATCH) / BM);
    gemm_gi_kernel<<<ggrid, 256>>>(x, Wi, bi, gi);

    // 2) persistent GRU scan
    scan_kernel<<<SCAN_BLOCKS, SCAN_THREADS>>>(h0, Wh, bhn, out_h, out_ys);
}